// round 5
// baseline (speedup 1.0000x reference)
#include <cuda_runtime.h>

#define SQ     2048
#define DMODEL 1024
#define NHEAD  16
#define HDIM   64
#define WIN    256
#define BATCH  2

// Scratch (no runtime allocation allowed): qkv [B,S,3D], mixed [B,S,D]
__device__ float g_qkv[BATCH * SQ * 3 * DMODEL];
__device__ float g_mixed[BATCH * SQ * DMODEL];

// ---------------------------------------------------------------------------
// SGEMM: C[M,N] = A[M,K] @ B[K,N] + bias[N]
// 128x128 block tile, BK=8, 256 threads, 8x8 microtile (split fragments).
// All problem dims are multiples of 128/8 — no edge handling needed.
// ---------------------------------------------------------------------------
__global__ __launch_bounds__(256, 2)
void sgemm_bias_kernel(const float* __restrict__ A, const float* __restrict__ B,
                       const float* __restrict__ bias, float* __restrict__ C,
                       int M, int N, int K)
{
    __shared__ float As[8][132];   // transposed A tile, padded (conflict-free)
    __shared__ float Bs[8][128];

    const int tid = threadIdx.x;
    const int tx = tid & 15;       // 0..15 -> N
    const int ty = tid >> 4;       // 0..15 -> M
    const int row0 = blockIdx.y * 128;
    const int col0 = blockIdx.x * 128;

    const int aRow = tid >> 1;         // 0..127
    const int aCol = (tid & 1) * 4;    // 0 or 4
    const int bRow = tid >> 5;         // 0..7
    const int bCol = (tid & 31) * 4;   // 0..124

    const float* Ag = A + (size_t)(row0 + aRow) * K + aCol;
    const float* Bg = B + (size_t)bRow * N + col0 + bCol;

    float acc[8][8];
#pragma unroll
    for (int i = 0; i < 8; i++)
#pragma unroll
        for (int j = 0; j < 8; j++) acc[i][j] = 0.f;

    for (int kk = 0; kk < K; kk += 8) {
        float4 av = *(const float4*)(Ag + kk);
        float4 bv = *(const float4*)(Bg + (size_t)kk * N);
        __syncthreads();   // previous tile's compute done
        As[aCol + 0][aRow] = av.x;
        As[aCol + 1][aRow] = av.y;
        As[aCol + 2][aRow] = av.z;
        As[aCol + 3][aRow] = av.w;
        *(float4*)(&Bs[bRow][bCol]) = bv;
        __syncthreads();

#pragma unroll
        for (int k = 0; k < 8; k++) {
            float4 a0 = *(const float4*)(&As[k][ty * 4]);
            float4 a1 = *(const float4*)(&As[k][64 + ty * 4]);
            float4 b0 = *(const float4*)(&Bs[k][tx * 4]);
            float4 b1 = *(const float4*)(&Bs[k][64 + tx * 4]);
            float a[8] = {a0.x, a0.y, a0.z, a0.w, a1.x, a1.y, a1.z, a1.w};
            float b[8] = {b0.x, b0.y, b0.z, b0.w, b1.x, b1.y, b1.z, b1.w};
#pragma unroll
            for (int i = 0; i < 8; i++)
#pragma unroll
                for (int j = 0; j < 8; j++) acc[i][j] += a[i] * b[j];
        }
    }

    // Epilogue: rows {ty*4+i, 64+ty*4+i}, cols {tx*4+j, 64+tx*4+j}
#pragma unroll
    for (int ii = 0; ii < 8; ii++) {
        int r = row0 + ((ii < 4) ? (ty * 4 + ii) : (64 + ty * 4 + ii - 4));
        int c0 = col0 + tx * 4;
        int c1 = col0 + 64 + tx * 4;
        float4 o0 = make_float4(acc[ii][0] + bias[c0 + 0], acc[ii][1] + bias[c0 + 1],
                                acc[ii][2] + bias[c0 + 2], acc[ii][3] + bias[c0 + 3]);
        float4 o1 = make_float4(acc[ii][4] + bias[c1 + 0], acc[ii][5] + bias[c1 + 1],
                                acc[ii][6] + bias[c1 + 2], acc[ii][7] + bias[c1 + 3]);
        *(float4*)(&C[(size_t)r * N + c0]) = o0;
        *(float4*)(&C[(size_t)r * N + c1]) = o1;
    }
}

// ---------------------------------------------------------------------------
// Fused local-causal flash attention.
// Grid: (S/64, H, B). Block: 256 threads (16x16), each thread owns a 4x4
// score/output microtile. Key tiles: at most 5 per query block (W=256).
// K is stored transposed in SMEM; P (probs) reuses K's buffer.
// Masked softmax == reference's additive -1e9 bias (exp underflows to 0).
// ---------------------------------------------------------------------------
__global__ __launch_bounds__(256)
void local_attn_kernel(const float* __restrict__ qkv, float* __restrict__ mixed)
{
    extern __shared__ float sm[];
    float* Qs = sm;                  // [64][64]
    float* KP = sm + 64 * 64;        // [64][65]  K^T (d-major), then P[q][k]
    float* Vs = sm + 64 * 64 + 64 * 65; // [64][64]

    const int qb = blockIdx.x;
    const int h  = blockIdx.y;
    const int b  = blockIdx.z;
    const int tid = threadIdx.x;
    const int tx = tid & 15;
    const int ty = tid >> 4;
    const int q0 = qb * 64;

    const float* base = qkv + (size_t)b * SQ * (3 * DMODEL) + h * HDIM;

    // Load Q tile (coalesced float4)
#pragma unroll
    for (int i = 0; i < 4; i++) {
        int idx = tid + i * 256;
        int r = idx >> 4, c4 = (idx & 15) * 4;
        *(float4*)(Qs + r * 64 + c4) =
            *(const float4*)(base + (size_t)(q0 + r) * (3 * DMODEL) + c4);
    }

    float m_i[4], l_i[4], o[4][4];
#pragma unroll
    for (int i = 0; i < 4; i++) {
        m_i[i] = -1e30f; l_i[i] = 0.f;
#pragma unroll
        for (int j = 0; j < 4; j++) o[i][j] = 0.f;
    }

    const int kt0 = (qb >= 4) ? (qb - 4) : 0;
    for (int kt = kt0; kt <= qb; kt++) {
        const int k0 = kt * 64;
        __syncthreads();  // previous tile's PV done before reloading K/V
        const float* kb = base + DMODEL;
        const float* vb = base + 2 * DMODEL;
#pragma unroll
        for (int i = 0; i < 4; i++) {
            int idx = tid + i * 256;
            int r = idx >> 4, c4 = (idx & 15) * 4;
            float4 kv = *(const float4*)(kb + (size_t)(k0 + r) * (3 * DMODEL) + c4);
            KP[(c4 + 0) * 65 + r] = kv.x;   // transpose: KP[d][k]
            KP[(c4 + 1) * 65 + r] = kv.y;
            KP[(c4 + 2) * 65 + r] = kv.z;
            KP[(c4 + 3) * 65 + r] = kv.w;
            *(float4*)(Vs + r * 64 + c4) =
                *(const float4*)(vb + (size_t)(k0 + r) * (3 * DMODEL) + c4);
        }
        __syncthreads();

        // S = Q @ K^T  (4x4 per thread)
        float s[4][4];
#pragma unroll
        for (int i = 0; i < 4; i++)
#pragma unroll
            for (int j = 0; j < 4; j++) s[i][j] = 0.f;
#pragma unroll 16
        for (int d = 0; d < 64; d++) {
            float qv[4], kv[4];
#pragma unroll
            for (int i = 0; i < 4; i++) qv[i] = Qs[(ty * 4 + i) * 64 + d];
#pragma unroll
            for (int j = 0; j < 4; j++) kv[j] = KP[d * 65 + tx * 4 + j];
#pragma unroll
            for (int i = 0; i < 4; i++)
#pragma unroll
                for (int j = 0; j < 4; j++) s[i][j] += qv[i] * kv[j];
        }

        // Mask + online softmax (row groups span the 16 tx lanes of a half-warp)
        float pr[4][4];
#pragma unroll
        for (int i = 0; i < 4; i++) {
            const int q = q0 + ty * 4 + i;
            float rmax = -1e30f;
#pragma unroll
            for (int j = 0; j < 4; j++) {
                const int k = k0 + tx * 4 + j;
                const bool ok = (k <= q) && (k + WIN > q);
                s[i][j] = ok ? s[i][j] * 0.125f : -1e30f;
                rmax = fmaxf(rmax, s[i][j]);
            }
#pragma unroll
            for (int off = 8; off; off >>= 1)
                rmax = fmaxf(rmax, __shfl_xor_sync(0xffffffffu, rmax, off));
            const float mnew = fmaxf(m_i[i], rmax);
            const float alpha = __expf(m_i[i] - mnew);
            float psum = 0.f;
#pragma unroll
            for (int j = 0; j < 4; j++) {
                float p = (s[i][j] > -1e29f) ? __expf(s[i][j] - mnew) : 0.f;
                pr[i][j] = p;
                psum += p;
            }
#pragma unroll
            for (int off = 8; off; off >>= 1)
                psum += __shfl_xor_sync(0xffffffffu, psum, off);
            l_i[i] = l_i[i] * alpha + psum;
            m_i[i] = mnew;
#pragma unroll
            for (int j = 0; j < 4; j++) o[i][j] *= alpha;
        }

        __syncthreads();  // everyone done reading K from KP
#pragma unroll
        for (int i = 0; i < 4; i++)
#pragma unroll
            for (int j = 0; j < 4; j++)
                KP[(ty * 4 + i) * 65 + tx * 4 + j] = pr[i][j];
        __syncthreads();

        // O += P @ V
#pragma unroll 16
        for (int k = 0; k < 64; k++) {
            float4 vv = *(const float4*)(Vs + k * 64 + tx * 4);
#pragma unroll
            for (int i = 0; i < 4; i++) {
                float p = KP[(ty * 4 + i) * 65 + k];
                o[i][0] += p * vv.x;
                o[i][1] += p * vv.y;
                o[i][2] += p * vv.z;
                o[i][3] += p * vv.w;
            }
        }
    }

    // Finalize: mixed[b, q, h*64 + d] = O / l
#pragma unroll
    for (int i = 0; i < 4; i++) {
        const float inv = 1.0f / l_i[i];
        float4 ov = make_float4(o[i][0] * inv, o[i][1] * inv, o[i][2] * inv, o[i][3] * inv);
        *(float4*)(mixed + ((size_t)b * SQ + q0 + ty * 4 + i) * DMODEL + h * HDIM + tx * 4) = ov;
    }
}

// ---------------------------------------------------------------------------
extern "C" void kernel_launch(void* const* d_in, const int* in_sizes, int n_in,
                              void* d_out, int out_size)
{
    const float* normed = (const float*)d_in[0];
    // d_in[1] = attn_mask: unused — mask is analytic (k<=q && k>=q-255)
    const float* Wqkv = (const float*)d_in[2];
    const float* bqkv = (const float*)d_in[3];
    const float* Wout = (const float*)d_in[4];
    const float* bout = (const float*)d_in[5];
    float* out = (float*)d_out;

    float *qkv_p, *mix_p;
    cudaGetSymbolAddress((void**)&qkv_p, g_qkv);
    cudaGetSymbolAddress((void**)&mix_p, g_mixed);

    const int attn_smem = (64 * 64 + 64 * 65 + 64 * 64) * (int)sizeof(float); // 49408
    cudaFuncSetAttribute(local_attn_kernel,
                         cudaFuncAttributeMaxDynamicSharedMemorySize, attn_smem);

    // 1) qkv = normed @ Wqkv + bqkv      [4096,1024]x[1024,3072]
    dim3 g1(3 * DMODEL / 128, (BATCH * SQ) / 128);
    sgemm_bias_kernel<<<g1, 256>>>(normed, Wqkv, bqkv, qkv_p,
                                   BATCH * SQ, 3 * DMODEL, DMODEL);

    // 2) fused local-causal attention -> mixed
    dim3 g2(SQ / 64, NHEAD, BATCH);
    local_attn_kernel<<<g2, 256, attn_smem>>>(qkv_p, mix_p);

    // 3) out = mixed @ Wout + bout       [4096,1024]x[1024,1024]
    dim3 g3(DMODEL / 128, (BATCH * SQ) / 128);
    sgemm_bias_kernel<<<g3, 256>>>(mix_p, Wout, bout, out,
                                   BATCH * SQ, DMODEL, DMODEL);
}

// round 10
// speedup vs baseline: 1.7076x; 1.7076x over previous
#include <cuda_runtime.h>
#include <cuda_bf16.h>
#include <cstdint>

#define SQ     2048
#define DMODEL 1024
#define NHEAD  16
#define HDIM   64
#define WIN    256
#define BATCH  2
#define MROWS  (BATCH * SQ)      // 4096
#define KDIM   1024
#define KEFF   (3 * KDIM)        // 3072: [hi | hi | lo] x [hi | lo | hi]
#define NCHK   (KEFF / 64)       // 48 K-chunks of 64 bf16

// fp32 scratch
__device__ float g_qkv[BATCH * SQ * 3 * DMODEL];
__device__ float g_mixed[BATCH * SQ * DMODEL];
// bf16 split operands, concatenated-K layout
__device__ __nv_bfloat16 g_a[MROWS * KEFF];              // activations [M, 3072]
__device__ __nv_bfloat16 g_w1[3 * DMODEL * KEFF];        // Wqkv^T      [3072, 3072]
__device__ __nv_bfloat16 g_w2[DMODEL * KEFF];            // Wout^T      [1024, 3072]

// ---------------------------------------------------------------------------
// PTX helpers (all sm_80-level — compiles at compute_103)
// ---------------------------------------------------------------------------
__device__ __forceinline__ uint32_t smem_u32(const void* p) {
    uint32_t a;
    asm("{ .reg .u64 t; cvta.to.shared.u64 t, %1; cvt.u32.u64 %0, t; }" : "=r"(a) : "l"(p));
    return a;
}
#define CP_ASYNC16(dst, src) \
    asm volatile("cp.async.cg.shared.global [%0], [%1], 16;" :: "r"(dst), "l"(src))
#define CP_COMMIT()  asm volatile("cp.async.commit_group;" ::: "memory")
#define CP_WAIT0()   asm volatile("cp.async.wait_group 0;" ::: "memory")
#define CP_WAIT1()   asm volatile("cp.async.wait_group 1;" ::: "memory")

#define LDSM_X4(r, addr) \
    asm volatile("ldmatrix.sync.aligned.m8n8.x4.shared.b16 {%0,%1,%2,%3}, [%4];" \
        : "=r"((r)[0]), "=r"((r)[1]), "=r"((r)[2]), "=r"((r)[3]) : "r"(addr))

#define MMA16816(c, a, b0, b1) \
    asm volatile("mma.sync.aligned.m16n8k16.row.col.f32.bf16.bf16.f32 " \
        "{%0,%1,%2,%3}, {%4,%5,%6,%7}, {%8,%9}, {%0,%1,%2,%3};" \
        : "+f"((c)[0]), "+f"((c)[1]), "+f"((c)[2]), "+f"((c)[3]) \
        : "r"((a)[0]), "r"((a)[1]), "r"((a)[2]), "r"((a)[3]), "r"(b0), "r"(b1))

// ---------------------------------------------------------------------------
// conv_act: X[M,1024] fp32 -> A''[M,3072] bf16 = [hi | hi | lo]
// ---------------------------------------------------------------------------
__global__ __launch_bounds__(256)
void conv_act_kernel(const float* __restrict__ X, __nv_bfloat16* __restrict__ A)
{
    size_t t = (size_t)blockIdx.x * 256 + threadIdx.x;  // one float4 each
    size_t m = t >> 8;                                  // 256 float4 per row
    int k4 = (int)(t & 255) * 4;
    float4 x = *(const float4*)(X + m * KDIM + k4);
    float xs[4] = {x.x, x.y, x.z, x.w};
    uint32_t hp[2], lp[2];
#pragma unroll
    for (int i = 0; i < 2; i++) {
        __nv_bfloat16 h0 = __float2bfloat16(xs[2 * i]);
        __nv_bfloat16 h1 = __float2bfloat16(xs[2 * i + 1]);
        __nv_bfloat16 l0 = __float2bfloat16(xs[2 * i] - __bfloat162float(h0));
        __nv_bfloat16 l1 = __float2bfloat16(xs[2 * i + 1] - __bfloat162float(h1));
        hp[i] = (uint32_t)__bfloat16_as_ushort(h0) | ((uint32_t)__bfloat16_as_ushort(h1) << 16);
        lp[i] = (uint32_t)__bfloat16_as_ushort(l0) | ((uint32_t)__bfloat16_as_ushort(l1) << 16);
    }
    __nv_bfloat16* row = A + m * KEFF;
    uint2 hv = make_uint2(hp[0], hp[1]);
    uint2 lv = make_uint2(lp[0], lp[1]);
    *(uint2*)(row + k4)            = hv;
    *(uint2*)(row + KDIM + k4)     = hv;
    *(uint2*)(row + 2 * KDIM + k4) = lv;
}

// ---------------------------------------------------------------------------
// conv_w: W[1024,N] fp32 -> B''[N,3072] bf16 (transposed) = [hi | lo | hi]
// ---------------------------------------------------------------------------
__global__ __launch_bounds__(256)
void conv_w_kernel(const float* __restrict__ W, __nv_bfloat16* __restrict__ Bw, int N)
{
    __shared__ float ts[32][33];
    int k0 = blockIdx.y * 32, n0 = blockIdx.x * 32;
    int tx = threadIdx.x, ty = threadIdx.y;   // (32, 8)
#pragma unroll
    for (int i = 0; i < 4; i++)
        ts[ty + i * 8][tx] = W[(size_t)(k0 + ty + i * 8) * N + n0 + tx];
    __syncthreads();
#pragma unroll
    for (int i = 0; i < 4; i++) {
        int n = n0 + ty + i * 8;
        int k = k0 + tx;
        float x = ts[tx][ty + i * 8];
        __nv_bfloat16 h = __float2bfloat16(x);
        __nv_bfloat16 l = __float2bfloat16(x - __bfloat162float(h));
        __nv_bfloat16* row = Bw + (size_t)n * KEFF;
        row[k]            = h;
        row[KDIM + k]     = l;
        row[2 * KDIM + k] = h;
    }
}

// ---------------------------------------------------------------------------
// bf16 mma.sync GEMM: C[M,N] = A''[M,KEFF] @ B''[N,KEFF]^T + bias, fp32 out.
// CTA tile 128x256, 512 threads (16 warps 2x8), warp tile 64x32.
// K-chunk 64, cp.async double-buffered, 144B-padded smem rows (conflict-free
// for both cp.async 16B stores and ldmatrix).
// ---------------------------------------------------------------------------
#define RSTR  144
#define ASMB  (128 * RSTR)          // 18432
#define BSMB  (256 * RSTR)          // 36864
#define BUFSZ (ASMB + BSMB)         // 55296
#define GSMEM (2 * BUFSZ)           // 110592

__global__ __launch_bounds__(512, 1)
void gemm_mma_kernel(const __nv_bfloat16* __restrict__ A,
                     const __nv_bfloat16* __restrict__ Bw,
                     const float* __restrict__ bias, float* __restrict__ C, int N)
{
    extern __shared__ char sm[];
    const uint32_t sb = smem_u32(sm);
    const int tid = threadIdx.x;
    const int lane = tid & 31, wid = tid >> 5;
    const int wm = wid & 1, wn = wid >> 1;          // 2 x 8 warps
    const int m0 = blockIdx.y * 128, n0 = blockIdx.x * 256;

    const char* Ag = (const char*)(A + (size_t)m0 * KEFF);
    const char* Bg = (const char*)(Bw + (size_t)n0 * KEFF);

    auto copy_chunk = [&](int c, int buf) {
        const uint32_t d = sb + buf * BUFSZ;
        const size_t kbyte = (size_t)c * 128;       // 64 bf16 = 128B
#pragma unroll
        for (int i = 0; i < 2; i++) {               // A: 1024 16B chunks
            int cc = tid + i * 512;
            int r = cc >> 3, kc = cc & 7;
            CP_ASYNC16(d + r * RSTR + kc * 16,
                       Ag + (size_t)r * (KEFF * 2) + kbyte + kc * 16);
        }
#pragma unroll
        for (int i = 0; i < 4; i++) {               // B: 2048 16B chunks
            int cc = tid + i * 512;
            int r = cc >> 3, kc = cc & 7;
            CP_ASYNC16(d + ASMB + r * RSTR + kc * 16,
                       Bg + (size_t)r * (KEFF * 2) + kbyte + kc * 16);
        }
        CP_COMMIT();
    };

    float acc[4][4][4];
#pragma unroll
    for (int i = 0; i < 4; i++)
#pragma unroll
        for (int j = 0; j < 4; j++)
#pragma unroll
            for (int e = 0; e < 4; e++) acc[i][j][e] = 0.f;

    copy_chunk(0, 0);

    for (int c = 0; c < NCHK; c++) {
        const int buf = c & 1;
        if (c + 1 < NCHK) { copy_chunk(c + 1, 1 - buf); CP_WAIT1(); }
        else               CP_WAIT0();
        __syncthreads();

        const uint32_t Ab = sb + buf * BUFSZ;
        const uint32_t Bb = Ab + ASMB;
#pragma unroll
        for (int s = 0; s < 4; s++) {               // 4 x k16 steps
            // B fragments: 2 ldmatrix.x4 -> n = wn*32 + [0..15], [16..31]
            uint32_t Bf[2][4];
#pragma unroll
            for (int g = 0; g < 2; g++) {
                int n = wn * 32 + g * 16 + (lane & 7) + ((lane >> 4) & 1) * 8;
                uint32_t addr = Bb + n * RSTR + s * 32 + ((lane >> 3) & 1) * 16;
                LDSM_X4(Bf[g], addr);
            }
#pragma unroll
            for (int mi = 0; mi < 4; mi++) {
                uint32_t Aa[4];
                int r = wm * 64 + mi * 16 + (lane & 15);
                uint32_t addr = Ab + r * RSTR + s * 32 + (lane >> 4) * 16;
                LDSM_X4(Aa, addr);
#pragma unroll
                for (int nj = 0; nj < 4; nj++) {
                    uint32_t b0 = Bf[nj >> 1][(nj & 1) * 2];
                    uint32_t b1 = Bf[nj >> 1][(nj & 1) * 2 + 1];
                    MMA16816(acc[mi][nj], Aa, b0, b1);
                }
            }
        }
        __syncthreads();
    }

    // Epilogue
    const int gr = lane >> 2, gc = (lane & 3) * 2;
#pragma unroll
    for (int mi = 0; mi < 4; mi++) {
#pragma unroll
        for (int nj = 0; nj < 4; nj++) {
            int row = m0 + wm * 64 + mi * 16 + gr;
            int col = n0 + wn * 32 + nj * 8 + gc;
            float b0v = bias[col], b1v = bias[col + 1];
            *(float2*)(&C[(size_t)row * N + col]) =
                make_float2(acc[mi][nj][0] + b0v, acc[mi][nj][1] + b1v);
            *(float2*)(&C[(size_t)(row + 8) * N + col]) =
                make_float2(acc[mi][nj][2] + b0v, acc[mi][nj][3] + b1v);
        }
    }
}

// ---------------------------------------------------------------------------
// Fused local-causal flash attention (known-correct fp32 version).
// ---------------------------------------------------------------------------
__global__ __launch_bounds__(256)
void local_attn_kernel(const float* __restrict__ qkv, float* __restrict__ mixed)
{
    extern __shared__ float smf[];
    float* Qs = smf;
    float* KP = smf + 64 * 64;
    float* Vs = smf + 64 * 64 + 64 * 65;

    const int qb = blockIdx.x;
    const int h  = blockIdx.y;
    const int b  = blockIdx.z;
    const int tid = threadIdx.x;
    const int tx = tid & 15;
    const int ty = tid >> 4;
    const int q0 = qb * 64;

    const float* base = qkv + (size_t)b * SQ * (3 * DMODEL) + h * HDIM;

#pragma unroll
    for (int i = 0; i < 4; i++) {
        int idx = tid + i * 256;
        int r = idx >> 4, c4 = (idx & 15) * 4;
        *(float4*)(Qs + r * 64 + c4) =
            *(const float4*)(base + (size_t)(q0 + r) * (3 * DMODEL) + c4);
    }

    float m_i[4], l_i[4], o[4][4];
#pragma unroll
    for (int i = 0; i < 4; i++) {
        m_i[i] = -1e30f; l_i[i] = 0.f;
#pragma unroll
        for (int j = 0; j < 4; j++) o[i][j] = 0.f;
    }

    const int kt0 = (qb >= 4) ? (qb - 4) : 0;
    for (int kt = kt0; kt <= qb; kt++) {
        const int k0 = kt * 64;
        __syncthreads();
        const float* kb = base + DMODEL;
        const float* vb = base + 2 * DMODEL;
#pragma unroll
        for (int i = 0; i < 4; i++) {
            int idx = tid + i * 256;
            int r = idx >> 4, c4 = (idx & 15) * 4;
            float4 kv = *(const float4*)(kb + (size_t)(k0 + r) * (3 * DMODEL) + c4);
            KP[(c4 + 0) * 65 + r] = kv.x;
            KP[(c4 + 1) * 65 + r] = kv.y;
            KP[(c4 + 2) * 65 + r] = kv.z;
            KP[(c4 + 3) * 65 + r] = kv.w;
            *(float4*)(Vs + r * 64 + c4) =
                *(const float4*)(vb + (size_t)(k0 + r) * (3 * DMODEL) + c4);
        }
        __syncthreads();

        float s[4][4];
#pragma unroll
        for (int i = 0; i < 4; i++)
#pragma unroll
            for (int j = 0; j < 4; j++) s[i][j] = 0.f;
#pragma unroll 16
        for (int d = 0; d < 64; d++) {
            float qv[4], kv[4];
#pragma unroll
            for (int i = 0; i < 4; i++) qv[i] = Qs[(ty * 4 + i) * 64 + d];
#pragma unroll
            for (int j = 0; j < 4; j++) kv[j] = KP[d * 65 + tx * 4 + j];
#pragma unroll
            for (int i = 0; i < 4; i++)
#pragma unroll
                for (int j = 0; j < 4; j++) s[i][j] += qv[i] * kv[j];
        }

        float pr[4][4];
#pragma unroll
        for (int i = 0; i < 4; i++) {
            const int q = q0 + ty * 4 + i;
            float rmax = -1e30f;
#pragma unroll
            for (int j = 0; j < 4; j++) {
                const int k = k0 + tx * 4 + j;
                const bool ok = (k <= q) && (k + WIN > q);
                s[i][j] = ok ? s[i][j] * 0.125f : -1e30f;
                rmax = fmaxf(rmax, s[i][j]);
            }
#pragma unroll
            for (int off = 8; off; off >>= 1)
                rmax = fmaxf(rmax, __shfl_xor_sync(0xffffffffu, rmax, off));
            const float mnew = fmaxf(m_i[i], rmax);
            const float alpha = __expf(m_i[i] - mnew);
            float psum = 0.f;
#pragma unroll
            for (int j = 0; j < 4; j++) {
                float p = (s[i][j] > -1e29f) ? __expf(s[i][j] - mnew) : 0.f;
                pr[i][j] = p;
                psum += p;
            }
#pragma unroll
            for (int off = 8; off; off >>= 1)
                psum += __shfl_xor_sync(0xffffffffu, psum, off);
            l_i[i] = l_i[i] * alpha + psum;
            m_i[i] = mnew;
#pragma unroll
            for (int j = 0; j < 4; j++) o[i][j] *= alpha;
        }

        __syncthreads();
#pragma unroll
        for (int i = 0; i < 4; i++)
#pragma unroll
            for (int j = 0; j < 4; j++)
                KP[(ty * 4 + i) * 65 + tx * 4 + j] = pr[i][j];
        __syncthreads();

#pragma unroll 16
        for (int k = 0; k < 64; k++) {
            float4 vv = *(const float4*)(Vs + k * 64 + tx * 4);
#pragma unroll
            for (int i = 0; i < 4; i++) {
                float p = KP[(ty * 4 + i) * 65 + k];
                o[i][0] += p * vv.x;
                o[i][1] += p * vv.y;
                o[i][2] += p * vv.z;
                o[i][3] += p * vv.w;
            }
        }
    }

#pragma unroll
    for (int i = 0; i < 4; i++) {
        const float inv = 1.0f / l_i[i];
        float4 ov = make_float4(o[i][0] * inv, o[i][1] * inv, o[i][2] * inv, o[i][3] * inv);
        *(float4*)(mixed + ((size_t)b * SQ + q0 + ty * 4 + i) * DMODEL + h * HDIM + tx * 4) = ov;
    }
}

// ---------------------------------------------------------------------------
extern "C" void kernel_launch(void* const* d_in, const int* in_sizes, int n_in,
                              void* d_out, int out_size)
{
    const float* normed = (const float*)d_in[0];
    // d_in[1] = attn_mask: analytic (k<=q && k>=q-255), unused
    const float* Wqkv = (const float*)d_in[2];
    const float* bqkv = (const float*)d_in[3];
    const float* Wout = (const float*)d_in[4];
    const float* bout = (const float*)d_in[5];
    float* out = (float*)d_out;

    float *qkv_p, *mix_p;
    __nv_bfloat16 *a_p, *w1_p, *w2_p;
    cudaGetSymbolAddress((void**)&qkv_p, g_qkv);
    cudaGetSymbolAddress((void**)&mix_p, g_mixed);
    cudaGetSymbolAddress((void**)&a_p, g_a);
    cudaGetSymbolAddress((void**)&w1_p, g_w1);
    cudaGetSymbolAddress((void**)&w2_p, g_w2);

    cudaFuncSetAttribute(gemm_mma_kernel,
                         cudaFuncAttributeMaxDynamicSharedMemorySize, GSMEM);
    const int attn_smem = (64 * 64 + 64 * 65 + 64 * 64) * (int)sizeof(float);
    cudaFuncSetAttribute(local_attn_kernel,
                         cudaFuncAttributeMaxDynamicSharedMemorySize, attn_smem);

    // 1) split/convert normed + Wqkv
    conv_act_kernel<<<MROWS, 256>>>(normed, a_p);
    conv_w_kernel<<<dim3(3 * DMODEL / 32, KDIM / 32), dim3(32, 8)>>>(Wqkv, w1_p, 3 * DMODEL);

    // 2) qkv = normed @ Wqkv + bqkv   (bf16 mma.sync, split-3 via K=3072)
    gemm_mma_kernel<<<dim3(3 * DMODEL / 256, MROWS / 128), 512, GSMEM>>>(
        a_p, w1_p, bqkv, qkv_p, 3 * DMODEL);

    // 3) fused local-causal attention
    dim3 g2(SQ / 64, NHEAD, BATCH);
    local_attn_kernel<<<g2, 256, attn_smem>>>(qkv_p, mix_p);

    // 4) split/convert mixed + Wout
    conv_act_kernel<<<MROWS, 256>>>(mix_p, a_p);
    conv_w_kernel<<<dim3(DMODEL / 32, KDIM / 32), dim3(32, 8)>>>(Wout, w2_p, DMODEL);

    // 5) out = mixed @ Wout + bout
    gemm_mma_kernel<<<dim3(DMODEL / 256, MROWS / 128), 512, GSMEM>>>(
        a_p, w2_p, bout, out, DMODEL);
}

// round 14
// speedup vs baseline: 1.8627x; 1.0908x over previous
#include <cuda_runtime.h>
#include <cuda_bf16.h>
#include <cstdint>

#define SQ     2048
#define DMODEL 1024
#define NHEAD  16
#define HDIM   64
#define WIN    256
#define BATCH  2
#define MROWS  (BATCH * SQ)      // 4096
#define KDIM   1024
#define NCHK   (KDIM / 64)       // 16 K-chunks of 64

// fp32 scratch
__device__ float g_qkv[BATCH * SQ * 3 * DMODEL];
__device__ float g_mixed[BATCH * SQ * DMODEL];
// bf16 split operands (separate hi/lo, row-major [*, 1024])
__device__ __nv_bfloat16 g_aHi[MROWS * KDIM];
__device__ __nv_bfloat16 g_aLo[MROWS * KDIM];
__device__ __nv_bfloat16 g_w1Hi[3 * DMODEL * KDIM];
__device__ __nv_bfloat16 g_w1Lo[3 * DMODEL * KDIM];
__device__ __nv_bfloat16 g_w2Hi[DMODEL * KDIM];
__device__ __nv_bfloat16 g_w2Lo[DMODEL * KDIM];

// ---------------------------------------------------------------------------
// PTX helpers (sm_80-level, compiles at compute_103)
// ---------------------------------------------------------------------------
__device__ __forceinline__ uint32_t smem_u32(const void* p) {
    uint32_t a;
    asm("{ .reg .u64 t; cvta.to.shared.u64 t, %1; cvt.u32.u64 %0, t; }" : "=r"(a) : "l"(p));
    return a;
}
#define CP_ASYNC16(dst, src) \
    asm volatile("cp.async.cg.shared.global [%0], [%1], 16;" :: "r"(dst), "l"(src))
#define CP_COMMIT()  asm volatile("cp.async.commit_group;" ::: "memory")
#define CP_WAIT0()   asm volatile("cp.async.wait_group 0;" ::: "memory")
#define CP_WAIT1()   asm volatile("cp.async.wait_group 1;" ::: "memory")

#define LDSM_X4(r, addr) \
    asm volatile("ldmatrix.sync.aligned.m8n8.x4.shared.b16 {%0,%1,%2,%3}, [%4];" \
        : "=r"((r)[0]), "=r"((r)[1]), "=r"((r)[2]), "=r"((r)[3]) : "r"(addr))

#define MMA16816(c, a, b0, b1) \
    asm volatile("mma.sync.aligned.m16n8k16.row.col.f32.bf16.bf16.f32 " \
        "{%0,%1,%2,%3}, {%4,%5,%6,%7}, {%8,%9}, {%0,%1,%2,%3};" \
        : "+f"((c)[0]), "+f"((c)[1]), "+f"((c)[2]), "+f"((c)[3]) \
        : "r"((a)[0]), "r"((a)[1]), "r"((a)[2]), "r"((a)[3]), "r"(b0), "r"(b1))

// ---------------------------------------------------------------------------
// conv_act: X[M,1024] fp32 -> hi/lo bf16 [M,1024] each
// ---------------------------------------------------------------------------
__global__ __launch_bounds__(256)
void conv_act_kernel(const float* __restrict__ X,
                     __nv_bfloat16* __restrict__ Hi, __nv_bfloat16* __restrict__ Lo)
{
    size_t t = (size_t)blockIdx.x * 256 + threadIdx.x;  // one float4 each
    size_t m = t >> 8;
    int k4 = (int)(t & 255) * 4;
    float4 x = *(const float4*)(X + m * KDIM + k4);
    float xs[4] = {x.x, x.y, x.z, x.w};
    uint32_t hp[2], lp[2];
#pragma unroll
    for (int i = 0; i < 2; i++) {
        __nv_bfloat16 h0 = __float2bfloat16(xs[2 * i]);
        __nv_bfloat16 h1 = __float2bfloat16(xs[2 * i + 1]);
        __nv_bfloat16 l0 = __float2bfloat16(xs[2 * i] - __bfloat162float(h0));
        __nv_bfloat16 l1 = __float2bfloat16(xs[2 * i + 1] - __bfloat162float(h1));
        hp[i] = (uint32_t)__bfloat16_as_ushort(h0) | ((uint32_t)__bfloat16_as_ushort(h1) << 16);
        lp[i] = (uint32_t)__bfloat16_as_ushort(l0) | ((uint32_t)__bfloat16_as_ushort(l1) << 16);
    }
    *(uint2*)(Hi + m * KDIM + k4) = make_uint2(hp[0], hp[1]);
    *(uint2*)(Lo + m * KDIM + k4) = make_uint2(lp[0], lp[1]);
}

// ---------------------------------------------------------------------------
// conv_w: W[1024,N] fp32 -> transposed hi/lo bf16 [N,1024]
// ---------------------------------------------------------------------------
__global__ __launch_bounds__(256)
void conv_w_kernel(const float* __restrict__ W,
                   __nv_bfloat16* __restrict__ Hi, __nv_bfloat16* __restrict__ Lo, int N)
{
    __shared__ float ts[32][33];
    int k0 = blockIdx.y * 32, n0 = blockIdx.x * 32;
    int tx = threadIdx.x, ty = threadIdx.y;   // (32, 8)
#pragma unroll
    for (int i = 0; i < 4; i++)
        ts[ty + i * 8][tx] = W[(size_t)(k0 + ty + i * 8) * N + n0 + tx];
    __syncthreads();
#pragma unroll
    for (int i = 0; i < 4; i++) {
        int n = n0 + ty + i * 8;
        int k = k0 + tx;
        float x = ts[tx][ty + i * 8];
        __nv_bfloat16 h = __float2bfloat16(x);
        __nv_bfloat16 l = __float2bfloat16(x - __bfloat162float(h));
        Hi[(size_t)n * KDIM + k] = h;
        Lo[(size_t)n * KDIM + k] = l;
    }
}

// ---------------------------------------------------------------------------
// 3-term bf16 mma.sync GEMM: C = (Ah+Al)(Bh+Bl)^T + bias  (drop Al*Bl)
// CTA tile 128x256, 256 threads (8 warps 2x4), warp tile 64x64.
// K-chunk 64 over K=1024; per chunk 3 MMA terms (hh, hl, lh) on resident smem.
// Double-buffered cp.async; 144B-padded rows.
// ---------------------------------------------------------------------------
#define RSTR  144
#define AONE  (128 * RSTR)            // 18432 per A matrix
#define BONE  (256 * RSTR)            // 36864 per B matrix
#define BUFSZ (2 * AONE + 2 * BONE)   // 110592
#define GSMEM (2 * BUFSZ)             // 221184

__global__ __launch_bounds__(256, 1)
void gemm_mma_kernel(const __nv_bfloat16* __restrict__ Ah_g,
                     const __nv_bfloat16* __restrict__ Al_g,
                     const __nv_bfloat16* __restrict__ Bh_g,
                     const __nv_bfloat16* __restrict__ Bl_g,
                     const float* __restrict__ bias, float* __restrict__ C, int N)
{
    extern __shared__ char sm[];
    const uint32_t sb = smem_u32(sm);
    const int tid = threadIdx.x;
    const int lane = tid & 31, wid = tid >> 5;
    const int wm = wid & 1, wn = wid >> 1;          // 2 x 4 warps, tile 64x64
    const int m0 = blockIdx.y * 128, n0 = blockIdx.x * 256;

    const char* AgH = (const char*)(Ah_g + (size_t)m0 * KDIM);
    const char* AgL = (const char*)(Al_g + (size_t)m0 * KDIM);
    const char* BgH = (const char*)(Bh_g + (size_t)n0 * KDIM);
    const char* BgL = (const char*)(Bl_g + (size_t)n0 * KDIM);

    // chunk smem layout: [Ah | Al | Bh | Bl]
    // A: 2 matrices x 128 rows x 8 units  = 2048 16B units (8 iters x 256 thr)
    // B: 2 matrices x 256 rows x 8 units  = 4096 16B units (16 iters x 256 thr)
    auto copy_chunk = [&](int c, int buf) {
        const uint32_t d = sb + buf * BUFSZ;
        const size_t kb = (size_t)c * 128;          // 64 bf16 = 128B
#pragma unroll
        for (int i = 0; i < 8; i++) {
            int u = tid + i * 256;                  // 0..2047
            int r = (u & 1023) >> 3, kc = u & 7;
            const char* src = (u < 1024) ? AgH : AgL;
            uint32_t dst = d + ((u < 1024) ? 0 : AONE) + r * RSTR + kc * 16;
            CP_ASYNC16(dst, src + (size_t)r * (KDIM * 2) + kb + kc * 16);
        }
#pragma unroll
        for (int i = 0; i < 16; i++) {
            int u = tid + i * 256;                  // 0..4095
            int r = (u & 2047) >> 3, kc = u & 7;
            const char* src = (u < 2048) ? BgH : BgL;
            uint32_t dst = d + 2 * AONE + ((u < 2048) ? 0 : BONE) + r * RSTR + kc * 16;
            CP_ASYNC16(dst, src + (size_t)r * (KDIM * 2) + kb + kc * 16);
        }
        CP_COMMIT();
    };

    float acc[4][8][4];
#pragma unroll
    for (int i = 0; i < 4; i++)
#pragma unroll
        for (int j = 0; j < 8; j++)
#pragma unroll
            for (int e = 0; e < 4; e++) acc[i][j][e] = 0.f;

    copy_chunk(0, 0);

    for (int c = 0; c < NCHK; c++) {
        const int buf = c & 1;
        if (c + 1 < NCHK) { copy_chunk(c + 1, 1 - buf); CP_WAIT1(); }
        else               CP_WAIT0();
        __syncthreads();

        const uint32_t AbH = sb + buf * BUFSZ;
        const uint32_t AbL = AbH + AONE;
        const uint32_t BbH = AbH + 2 * AONE;
        const uint32_t BbL = BbH + BONE;
#pragma unroll
        for (int s = 0; s < 4; s++) {               // 4 x k16 steps
            const uint32_t koff = s * 32 + ((lane >> 4) & 1) * 16;
            const uint32_t koffB = s * 32 + ((lane >> 3) & 1) * 16;
            // B fragments hi+lo: n = wn*64 + g*16 + ...
            uint32_t Bh[4][4], Bl[4][4];
#pragma unroll
            for (int g = 0; g < 4; g++) {
                int n = wn * 64 + g * 16 + (lane & 7) + ((lane >> 4) & 1) * 8;
                LDSM_X4(Bh[g], BbH + n * RSTR + koffB);
                LDSM_X4(Bl[g], BbL + n * RSTR + koffB);
            }
#pragma unroll
            for (int mi = 0; mi < 4; mi++) {
                int r = wm * 64 + mi * 16 + (lane & 15);
                uint32_t Aa[4];
                LDSM_X4(Aa, AbH + r * RSTR + koff);     // A hi
#pragma unroll
                for (int nj = 0; nj < 8; nj++) {        // hh
                    uint32_t* Bf = Bh[nj >> 1];
                    MMA16816(acc[mi][nj], Aa, Bf[(nj & 1) * 2], Bf[(nj & 1) * 2 + 1]);
                }
#pragma unroll
                for (int nj = 0; nj < 8; nj++) {        // hl
                    uint32_t* Bf = Bl[nj >> 1];
                    MMA16816(acc[mi][nj], Aa, Bf[(nj & 1) * 2], Bf[(nj & 1) * 2 + 1]);
                }
                LDSM_X4(Aa, AbL + r * RSTR + koff);     // A lo
#pragma unroll
                for (int nj = 0; nj < 8; nj++) {        // lh
                    uint32_t* Bf = Bh[nj >> 1];
                    MMA16816(acc[mi][nj], Aa, Bf[(nj & 1) * 2], Bf[(nj & 1) * 2 + 1]);
                }
            }
        }
        __syncthreads();
    }

    // Epilogue
    const int gr = lane >> 2, gc = (lane & 3) * 2;
#pragma unroll
    for (int mi = 0; mi < 4; mi++) {
#pragma unroll
        for (int nj = 0; nj < 8; nj++) {
            int row = m0 + wm * 64 + mi * 16 + gr;
            int col = n0 + wn * 64 + nj * 8 + gc;
            float b0v = bias[col], b1v = bias[col + 1];
            *(float2*)(&C[(size_t)row * N + col]) =
                make_float2(acc[mi][nj][0] + b0v, acc[mi][nj][1] + b1v);
            *(float2*)(&C[(size_t)(row + 8) * N + col]) =
                make_float2(acc[mi][nj][2] + b0v, acc[mi][nj][3] + b1v);
        }
    }
}

// ---------------------------------------------------------------------------
// Fused local-causal flash attention (verified fp32 version, unchanged).
// ---------------------------------------------------------------------------
__global__ __launch_bounds__(256)
void local_attn_kernel(const float* __restrict__ qkv, float* __restrict__ mixed)
{
    extern __shared__ float smf[];
    float* Qs = smf;
    float* KP = smf + 64 * 64;
    float* Vs = smf + 64 * 64 + 64 * 65;

    const int qb = blockIdx.x;
    const int h  = blockIdx.y;
    const int b  = blockIdx.z;
    const int tid = threadIdx.x;
    const int tx = tid & 15;
    const int ty = tid >> 4;
    const int q0 = qb * 64;

    const float* base = qkv + (size_t)b * SQ * (3 * DMODEL) + h * HDIM;

#pragma unroll
    for (int i = 0; i < 4; i++) {
        int idx = tid + i * 256;
        int r = idx >> 4, c4 = (idx & 15) * 4;
        *(float4*)(Qs + r * 64 + c4) =
            *(const float4*)(base + (size_t)(q0 + r) * (3 * DMODEL) + c4);
    }

    float m_i[4], l_i[4], o[4][4];
#pragma unroll
    for (int i = 0; i < 4; i++) {
        m_i[i] = -1e30f; l_i[i] = 0.f;
#pragma unroll
        for (int j = 0; j < 4; j++) o[i][j] = 0.f;
    }

    const int kt0 = (qb >= 4) ? (qb - 4) : 0;
    for (int kt = kt0; kt <= qb; kt++) {
        const int k0 = kt * 64;
        __syncthreads();
        const float* kb = base + DMODEL;
        const float* vb = base + 2 * DMODEL;
#pragma unroll
        for (int i = 0; i < 4; i++) {
            int idx = tid + i * 256;
            int r = idx >> 4, c4 = (idx & 15) * 4;
            float4 kv = *(const float4*)(kb + (size_t)(k0 + r) * (3 * DMODEL) + c4);
            KP[(c4 + 0) * 65 + r] = kv.x;
            KP[(c4 + 1) * 65 + r] = kv.y;
            KP[(c4 + 2) * 65 + r] = kv.z;
            KP[(c4 + 3) * 65 + r] = kv.w;
            *(float4*)(Vs + r * 64 + c4) =
                *(const float4*)(vb + (size_t)(k0 + r) * (3 * DMODEL) + c4);
        }
        __syncthreads();

        float s[4][4];
#pragma unroll
        for (int i = 0; i < 4; i++)
#pragma unroll
            for (int j = 0; j < 4; j++) s[i][j] = 0.f;
#pragma unroll 16
        for (int d = 0; d < 64; d++) {
            float qv[4], kv[4];
#pragma unroll
            for (int i = 0; i < 4; i++) qv[i] = Qs[(ty * 4 + i) * 64 + d];
#pragma unroll
            for (int j = 0; j < 4; j++) kv[j] = KP[d * 65 + tx * 4 + j];
#pragma unroll
            for (int i = 0; i < 4; i++)
#pragma unroll
                for (int j = 0; j < 4; j++) s[i][j] += qv[i] * kv[j];
        }

        float pr[4][4];
#pragma unroll
        for (int i = 0; i < 4; i++) {
            const int q = q0 + ty * 4 + i;
            float rmax = -1e30f;
#pragma unroll
            for (int j = 0; j < 4; j++) {
                const int k = k0 + tx * 4 + j;
                const bool ok = (k <= q) && (k + WIN > q);
                s[i][j] = ok ? s[i][j] * 0.125f : -1e30f;
                rmax = fmaxf(rmax, s[i][j]);
            }
#pragma unroll
            for (int off = 8; off; off >>= 1)
                rmax = fmaxf(rmax, __shfl_xor_sync(0xffffffffu, rmax, off));
            const float mnew = fmaxf(m_i[i], rmax);
            const float alpha = __expf(m_i[i] - mnew);
            float psum = 0.f;
#pragma unroll
            for (int j = 0; j < 4; j++) {
                float p = (s[i][j] > -1e29f) ? __expf(s[i][j] - mnew) : 0.f;
                pr[i][j] = p;
                psum += p;
            }
#pragma unroll
            for (int off = 8; off; off >>= 1)
                psum += __shfl_xor_sync(0xffffffffu, psum, off);
            l_i[i] = l_i[i] * alpha + psum;
            m_i[i] = mnew;
#pragma unroll
            for (int j = 0; j < 4; j++) o[i][j] *= alpha;
        }

        __syncthreads();
#pragma unroll
        for (int i = 0; i < 4; i++)
#pragma unroll
            for (int j = 0; j < 4; j++)
                KP[(ty * 4 + i) * 65 + tx * 4 + j] = pr[i][j];
        __syncthreads();

#pragma unroll 16
        for (int k = 0; k < 64; k++) {
            float4 vv = *(const float4*)(Vs + k * 64 + tx * 4);
#pragma unroll
            for (int i = 0; i < 4; i++) {
                float p = KP[(ty * 4 + i) * 65 + k];
                o[i][0] += p * vv.x;
                o[i][1] += p * vv.y;
                o[i][2] += p * vv.z;
                o[i][3] += p * vv.w;
            }
        }
    }

#pragma unroll
    for (int i = 0; i < 4; i++) {
        const float inv = 1.0f / l_i[i];
        float4 ov = make_float4(o[i][0] * inv, o[i][1] * inv, o[i][2] * inv, o[i][3] * inv);
        *(float4*)(mixed + ((size_t)b * SQ + q0 + ty * 4 + i) * DMODEL + h * HDIM + tx * 4) = ov;
    }
}

// ---------------------------------------------------------------------------
extern "C" void kernel_launch(void* const* d_in, const int* in_sizes, int n_in,
                              void* d_out, int out_size)
{
    const float* normed = (const float*)d_in[0];
    // d_in[1] = attn_mask: analytic (k<=q && k>=q-255), unused
    const float* Wqkv = (const float*)d_in[2];
    const float* bqkv = (const float*)d_in[3];
    const float* Wout = (const float*)d_in[4];
    const float* bout = (const float*)d_in[5];
    float* out = (float*)d_out;

    float *qkv_p, *mix_p;
    __nv_bfloat16 *aHi, *aLo, *w1Hi, *w1Lo, *w2Hi, *w2Lo;
    cudaGetSymbolAddress((void**)&qkv_p, g_qkv);
    cudaGetSymbolAddress((void**)&mix_p, g_mixed);
    cudaGetSymbolAddress((void**)&aHi, g_aHi);
    cudaGetSymbolAddress((void**)&aLo, g_aLo);
    cudaGetSymbolAddress((void**)&w1Hi, g_w1Hi);
    cudaGetSymbolAddress((void**)&w1Lo, g_w1Lo);
    cudaGetSymbolAddress((void**)&w2Hi, g_w2Hi);
    cudaGetSymbolAddress((void**)&w2Lo, g_w2Lo);

    cudaFuncSetAttribute(gemm_mma_kernel,
                         cudaFuncAttributeMaxDynamicSharedMemorySize, GSMEM);
    const int attn_smem = (64 * 64 + 64 * 65 + 64 * 64) * (int)sizeof(float);
    cudaFuncSetAttribute(local_attn_kernel,
                         cudaFuncAttributeMaxDynamicSharedMemorySize, attn_smem);

    // 1) split/convert normed + Wqkv
    conv_act_kernel<<<MROWS, 256>>>(normed, aHi, aLo);
    conv_w_kernel<<<dim3(3 * DMODEL / 32, KDIM / 32), dim3(32, 8)>>>(Wqkv, w1Hi, w1Lo, 3 * DMODEL);

    // 2) qkv = normed @ Wqkv + bqkv   (3-term bf16 split, resident per chunk)
    gemm_mma_kernel<<<dim3(3 * DMODEL / 256, MROWS / 128), 256, GSMEM>>>(
        aHi, aLo, w1Hi, w1Lo, bqkv, qkv_p, 3 * DMODEL);

    // 3) fused local-causal attention
    dim3 g2(SQ / 64, NHEAD, BATCH);
    local_attn_kernel<<<g2, 256, attn_smem>>>(qkv_p, mix_p);

    // 4) split/convert mixed + Wout
    conv_act_kernel<<<MROWS, 256>>>(mix_p, aHi, aLo);
    conv_w_kernel<<<dim3(DMODEL / 32, KDIM / 32), dim3(32, 8)>>>(Wout, w2Hi, w2Lo, DMODEL);

    // 5) out = mixed @ Wout + bout
    gemm_mma_kernel<<<dim3(DMODEL / 256, MROWS / 128), 256, GSMEM>>>(
        aHi, aLo, w2Hi, w2Lo, bout, out, DMODEL);
}

// round 15
// speedup vs baseline: 2.4080x; 1.2927x over previous
#include <cuda_runtime.h>
#include <cuda_bf16.h>
#include <cstdint>

#define SQ     2048
#define DMODEL 1024
#define NHEAD  16
#define HDIM   64
#define WIN    256
#define BATCH  2
#define MROWS  (BATCH * SQ)      // 4096
#define KDIM   1024
#define NCHK   (KDIM / 64)       // 16 K-chunks of 64

// bf16 split operands (separate hi/lo, row-major [*, 1024])
__device__ __nv_bfloat16 g_aHi[MROWS * KDIM];
__device__ __nv_bfloat16 g_aLo[MROWS * KDIM];
__device__ __nv_bfloat16 g_w1Hi[3 * DMODEL * KDIM];
__device__ __nv_bfloat16 g_w1Lo[3 * DMODEL * KDIM];
__device__ __nv_bfloat16 g_w2Hi[DMODEL * KDIM];
__device__ __nv_bfloat16 g_w2Lo[DMODEL * KDIM];
// split qkv written by GEMM1 epilogue [MROWS, 3*DMODEL]
__device__ __nv_bfloat16 g_qkvHi[MROWS * 3 * DMODEL];
__device__ __nv_bfloat16 g_qkvLo[MROWS * 3 * DMODEL];

// ---------------------------------------------------------------------------
// PTX helpers (sm_80-level, compiles at compute_103)
// ---------------------------------------------------------------------------
__device__ __forceinline__ uint32_t smem_u32(const void* p) {
    uint32_t a;
    asm("{ .reg .u64 t; cvta.to.shared.u64 t, %1; cvt.u32.u64 %0, t; }" : "=r"(a) : "l"(p));
    return a;
}
#define CP_ASYNC16(dst, src) \
    asm volatile("cp.async.cg.shared.global [%0], [%1], 16;" :: "r"(dst), "l"(src))
#define CP_COMMIT()  asm volatile("cp.async.commit_group;" ::: "memory")
#define CP_WAIT0()   asm volatile("cp.async.wait_group 0;" ::: "memory")
#define CP_WAIT1()   asm volatile("cp.async.wait_group 1;" ::: "memory")

#define LDSM_X4(r, addr) \
    asm volatile("ldmatrix.sync.aligned.m8n8.x4.shared.b16 {%0,%1,%2,%3}, [%4];" \
        : "=r"((r)[0]), "=r"((r)[1]), "=r"((r)[2]), "=r"((r)[3]) : "r"(addr))
#define LDSM_X4_T(r, addr) \
    asm volatile("ldmatrix.sync.aligned.m8n8.x4.trans.shared.b16 {%0,%1,%2,%3}, [%4];" \
        : "=r"((r)[0]), "=r"((r)[1]), "=r"((r)[2]), "=r"((r)[3]) : "r"(addr))

#define MMA16816(c, a, b0, b1) \
    asm volatile("mma.sync.aligned.m16n8k16.row.col.f32.bf16.bf16.f32 " \
        "{%0,%1,%2,%3}, {%4,%5,%6,%7}, {%8,%9}, {%0,%1,%2,%3};" \
        : "+f"((c)[0]), "+f"((c)[1]), "+f"((c)[2]), "+f"((c)[3]) \
        : "r"((a)[0]), "r"((a)[1]), "r"((a)[2]), "r"((a)[3]), "r"(b0), "r"(b1))

// split (a,b) fp32 pair into packed bf16x2 hi and lo (low half = a)
__device__ __forceinline__ void split2(float a, float b, uint32_t& hi, uint32_t& lo) {
    __nv_bfloat162 h = __floats2bfloat162_rn(a, b);
    float2 hf = __bfloat1622float2(h);
    __nv_bfloat162 l = __floats2bfloat162_rn(a - hf.x, b - hf.y);
    hi = *reinterpret_cast<uint32_t*>(&h);
    lo = *reinterpret_cast<uint32_t*>(&l);
}

// ---------------------------------------------------------------------------
// conv_act: X[M,1024] fp32 -> hi/lo bf16 [M,1024] each (pass 1 only)
// ---------------------------------------------------------------------------
__global__ __launch_bounds__(256)
void conv_act_kernel(const float* __restrict__ X,
                     __nv_bfloat16* __restrict__ Hi, __nv_bfloat16* __restrict__ Lo)
{
    size_t t = (size_t)blockIdx.x * 256 + threadIdx.x;  // one float4 each
    size_t m = t >> 8;
    int k4 = (int)(t & 255) * 4;
    float4 x = *(const float4*)(X + m * KDIM + k4);
    uint32_t h0, l0, h1, l1;
    split2(x.x, x.y, h0, l0);
    split2(x.z, x.w, h1, l1);
    *(uint2*)(Hi + m * KDIM + k4) = make_uint2(h0, h1);
    *(uint2*)(Lo + m * KDIM + k4) = make_uint2(l0, l1);
}

// ---------------------------------------------------------------------------
// conv_w: W[1024,N] fp32 -> transposed hi/lo bf16 [N,1024]
// ---------------------------------------------------------------------------
__global__ __launch_bounds__(256)
void conv_w_kernel(const float* __restrict__ W,
                   __nv_bfloat16* __restrict__ Hi, __nv_bfloat16* __restrict__ Lo, int N)
{
    __shared__ float ts[32][33];
    int k0 = blockIdx.y * 32, n0 = blockIdx.x * 32;
    int tx = threadIdx.x, ty = threadIdx.y;   // (32, 8)
#pragma unroll
    for (int i = 0; i < 4; i++)
        ts[ty + i * 8][tx] = W[(size_t)(k0 + ty + i * 8) * N + n0 + tx];
    __syncthreads();
#pragma unroll
    for (int i = 0; i < 4; i++) {
        int n = n0 + ty + i * 8;
        int k = k0 + tx;
        float x = ts[tx][ty + i * 8];
        __nv_bfloat16 h = __float2bfloat16(x);
        __nv_bfloat16 l = __float2bfloat16(x - __bfloat162float(h));
        Hi[(size_t)n * KDIM + k] = h;
        Lo[(size_t)n * KDIM + k] = l;
    }
}

// ---------------------------------------------------------------------------
// 3-term bf16 mma.sync GEMM: C = (Ah+Al)(Bh+Bl)^T + bias  (drop Al*Bl)
// CTA tile 128x256, 256 threads (8 warps 2x4), warp tile 64x64.
// Epilogue writes fp32 C (if non-null) and/or split bf16 Chi/Clo (if non-null).
// ---------------------------------------------------------------------------
#define RSTR  144
#define AONE  (128 * RSTR)            // 18432 per A matrix
#define BONE  (256 * RSTR)            // 36864 per B matrix
#define BUFSZ (2 * AONE + 2 * BONE)   // 110592
#define GSMEM (2 * BUFSZ)             // 221184

__global__ __launch_bounds__(256, 1)
void gemm_mma_kernel(const __nv_bfloat16* __restrict__ Ah_g,
                     const __nv_bfloat16* __restrict__ Al_g,
                     const __nv_bfloat16* __restrict__ Bh_g,
                     const __nv_bfloat16* __restrict__ Bl_g,
                     const float* __restrict__ bias, float* __restrict__ C,
                     __nv_bfloat16* __restrict__ Chi, __nv_bfloat16* __restrict__ Clo,
                     int N)
{
    extern __shared__ char sm[];
    const uint32_t sb = smem_u32(sm);
    const int tid = threadIdx.x;
    const int lane = tid & 31, wid = tid >> 5;
    const int wm = wid & 1, wn = wid >> 1;          // 2 x 4 warps, tile 64x64
    const int m0 = blockIdx.y * 128, n0 = blockIdx.x * 256;

    const char* AgH = (const char*)(Ah_g + (size_t)m0 * KDIM);
    const char* AgL = (const char*)(Al_g + (size_t)m0 * KDIM);
    const char* BgH = (const char*)(Bh_g + (size_t)n0 * KDIM);
    const char* BgL = (const char*)(Bl_g + (size_t)n0 * KDIM);

    auto copy_chunk = [&](int c, int buf) {
        const uint32_t d = sb + buf * BUFSZ;
        const size_t kb = (size_t)c * 128;          // 64 bf16 = 128B
#pragma unroll
        for (int i = 0; i < 8; i++) {
            int u = tid + i * 256;                  // 0..2047
            int r = (u & 1023) >> 3, kc = u & 7;
            const char* src = (u < 1024) ? AgH : AgL;
            uint32_t dst = d + ((u < 1024) ? 0 : AONE) + r * RSTR + kc * 16;
            CP_ASYNC16(dst, src + (size_t)r * (KDIM * 2) + kb + kc * 16);
        }
#pragma unroll
        for (int i = 0; i < 16; i++) {
            int u = tid + i * 256;                  // 0..4095
            int r = (u & 2047) >> 3, kc = u & 7;
            const char* src = (u < 2048) ? BgH : BgL;
            uint32_t dst = d + 2 * AONE + ((u < 2048) ? 0 : BONE) + r * RSTR + kc * 16;
            CP_ASYNC16(dst, src + (size_t)r * (KDIM * 2) + kb + kc * 16);
        }
        CP_COMMIT();
    };

    float acc[4][8][4];
#pragma unroll
    for (int i = 0; i < 4; i++)
#pragma unroll
        for (int j = 0; j < 8; j++)
#pragma unroll
            for (int e = 0; e < 4; e++) acc[i][j][e] = 0.f;

    copy_chunk(0, 0);

    for (int c = 0; c < NCHK; c++) {
        const int buf = c & 1;
        if (c + 1 < NCHK) { copy_chunk(c + 1, 1 - buf); CP_WAIT1(); }
        else               CP_WAIT0();
        __syncthreads();

        const uint32_t AbH = sb + buf * BUFSZ;
        const uint32_t AbL = AbH + AONE;
        const uint32_t BbH = AbH + 2 * AONE;
        const uint32_t BbL = BbH + BONE;
#pragma unroll
        for (int s = 0; s < 4; s++) {
            const uint32_t koff = s * 32 + ((lane >> 4) & 1) * 16;
            const uint32_t koffB = s * 32 + ((lane >> 3) & 1) * 16;
            uint32_t Bh[4][4], Bl[4][4];
#pragma unroll
            for (int g = 0; g < 4; g++) {
                int n = wn * 64 + g * 16 + (lane & 7) + ((lane >> 4) & 1) * 8;
                LDSM_X4(Bh[g], BbH + n * RSTR + koffB);
                LDSM_X4(Bl[g], BbL + n * RSTR + koffB);
            }
#pragma unroll
            for (int mi = 0; mi < 4; mi++) {
                int r = wm * 64 + mi * 16 + (lane & 15);
                uint32_t Aa[4];
                LDSM_X4(Aa, AbH + r * RSTR + koff);     // A hi
#pragma unroll
                for (int nj = 0; nj < 8; nj++) {        // hh
                    uint32_t* Bf = Bh[nj >> 1];
                    MMA16816(acc[mi][nj], Aa, Bf[(nj & 1) * 2], Bf[(nj & 1) * 2 + 1]);
                }
#pragma unroll
                for (int nj = 0; nj < 8; nj++) {        // hl
                    uint32_t* Bf = Bl[nj >> 1];
                    MMA16816(acc[mi][nj], Aa, Bf[(nj & 1) * 2], Bf[(nj & 1) * 2 + 1]);
                }
                LDSM_X4(Aa, AbL + r * RSTR + koff);     // A lo
#pragma unroll
                for (int nj = 0; nj < 8; nj++) {        // lh
                    uint32_t* Bf = Bh[nj >> 1];
                    MMA16816(acc[mi][nj], Aa, Bf[(nj & 1) * 2], Bf[(nj & 1) * 2 + 1]);
                }
            }
        }
        __syncthreads();
    }

    // Epilogue
    const int gr = lane >> 2, gc = (lane & 3) * 2;
#pragma unroll
    for (int mi = 0; mi < 4; mi++) {
#pragma unroll
        for (int nj = 0; nj < 8; nj++) {
            int row = m0 + wm * 64 + mi * 16 + gr;
            int col = n0 + wn * 64 + nj * 8 + gc;
            float b0v = bias[col], b1v = bias[col + 1];
            float v0 = acc[mi][nj][0] + b0v, v1 = acc[mi][nj][1] + b1v;
            float v2 = acc[mi][nj][2] + b0v, v3 = acc[mi][nj][3] + b1v;
            if (C) {
                *(float2*)(&C[(size_t)row * N + col]) = make_float2(v0, v1);
                *(float2*)(&C[(size_t)(row + 8) * N + col]) = make_float2(v2, v3);
            }
            if (Chi) {
                uint32_t h, l;
                split2(v0, v1, h, l);
                *(uint32_t*)(Chi + (size_t)row * N + col) = h;
                *(uint32_t*)(Clo + (size_t)row * N + col) = l;
                split2(v2, v3, h, l);
                *(uint32_t*)(Chi + (size_t)(row + 8) * N + col) = h;
                *(uint32_t*)(Clo + (size_t)(row + 8) * N + col) = l;
            }
        }
    }
}

// ---------------------------------------------------------------------------
// Tensor-core local-causal flash attention.
// Grid (SQ/64, H, B), 128 threads (4 warps), warp = 16 q-rows x 64 keys.
// S = QK^T (3-term bf16 split, fp32 acc), register softmax, P split hi/lo,
// O += P@V (3-term, V via ldmatrix.trans). Writes split bf16 mixed.
// ---------------------------------------------------------------------------
#define ARS   144
#define ATILE (64 * ARS)              // 9216
#define ASMEM (6 * ATILE)             // 55296

__global__ __launch_bounds__(128)
void attn_mma_kernel(const __nv_bfloat16* __restrict__ qkvHi,
                     const __nv_bfloat16* __restrict__ qkvLo,
                     __nv_bfloat16* __restrict__ mixHi,
                     __nv_bfloat16* __restrict__ mixLo)
{
    extern __shared__ char smc[];
    const uint32_t sb = smem_u32(smc);
    const uint32_t sQh = sb,             sQl = sb + ATILE;
    const uint32_t sKh = sb + 2 * ATILE, sKl = sb + 3 * ATILE;
    const uint32_t sVh = sb + 4 * ATILE, sVl = sb + 5 * ATILE;

    const int qb = blockIdx.x, h = blockIdx.y, b = blockIdx.z;
    const int tid = threadIdx.x, lane = tid & 31, w = tid >> 5;
    const int q0 = qb * 64;
    const int gr = lane >> 2;
    const int gc2 = (lane & 3) * 2;

    const size_t rs = 3 * DMODEL;
    const __nv_bfloat16* qkH = qkvHi + (size_t)b * SQ * rs + h * HDIM;
    const __nv_bfloat16* qkL = qkvLo + (size_t)b * SQ * rs + h * HDIM;

    // Q tile: 2 matrices x 64 rows x 8 16B-units = 1024 units, 8 per thread
#pragma unroll
    for (int i = 0; i < 8; i++) {
        int u = tid + i * 128;
        int r = (u >> 3) & 63;
        int un = u & 7;
        const __nv_bfloat16* src = (u < 512) ? qkH : qkL;
        uint32_t dst = ((u < 512) ? sQh : sQl) + r * ARS + un * 16;
        CP_ASYNC16(dst, (const char*)(src + (size_t)(q0 + r) * rs) + un * 16);
    }
    const int kt0 = (qb >= 4) ? (qb - 4) : 0;
    auto load_kv = [&](int kt) {
        int k0 = kt * 64;
#pragma unroll
        for (int i = 0; i < 16; i++) {
            int u = tid + i * 128;      // 0..2047
            int r = (u >> 3) & 63;
            int un = u & 7;
            int sel = u >> 9;           // 0:Kh 1:Kl 2:Vh 3:Vl
            const __nv_bfloat16* src = (sel == 0) ? qkH + DMODEL :
                                       (sel == 1) ? qkL + DMODEL :
                                       (sel == 2) ? qkH + 2 * DMODEL : qkL + 2 * DMODEL;
            uint32_t dstb = (sel == 0) ? sKh : (sel == 1) ? sKl :
                            (sel == 2) ? sVh : sVl;
            CP_ASYNC16(dstb + r * ARS + un * 16,
                       (const char*)(src + (size_t)(k0 + r) * rs) + un * 16);
        }
        CP_COMMIT();
    };
    load_kv(kt0);
    CP_WAIT0();
    __syncthreads();

    float m0_ = -1e30f, m1_ = -1e30f, l0 = 0.f, l1 = 0.f;
    float O[8][4];
#pragma unroll
    for (int j = 0; j < 8; j++)
#pragma unroll
        for (int e = 0; e < 4; e++) O[j][e] = 0.f;

    for (int kt = kt0; kt <= qb; kt++) {
        const int k0 = kt * 64;

        // ---- S = Q @ K^T (3-term) ----
        float sS[8][4];
#pragma unroll
        for (int j = 0; j < 8; j++)
#pragma unroll
            for (int e = 0; e < 4; e++) sS[j][e] = 0.f;

#pragma unroll
        for (int s = 0; s < 4; s++) {
            uint32_t Aq[4], Alr[4];
            {
                int r = w * 16 + (lane & 15);
                uint32_t koff = s * 32 + ((lane >> 4) & 1) * 16;
                LDSM_X4(Aq, sQh + r * ARS + koff);
                LDSM_X4(Alr, sQl + r * ARS + koff);
            }
            uint32_t Bh4[4][4], Bl4[4][4];
            {
                int n = (lane & 7) + ((lane >> 4) & 1) * 8;
                uint32_t koffB = s * 32 + ((lane >> 3) & 1) * 16;
#pragma unroll
                for (int g = 0; g < 4; g++) {
                    LDSM_X4(Bh4[g], sKh + (g * 16 + n) * ARS + koffB);
                    LDSM_X4(Bl4[g], sKl + (g * 16 + n) * ARS + koffB);
                }
            }
#pragma unroll
            for (int j = 0; j < 8; j++) {
                uint32_t b0h = Bh4[j >> 1][(j & 1) * 2], b1h = Bh4[j >> 1][(j & 1) * 2 + 1];
                uint32_t b0l = Bl4[j >> 1][(j & 1) * 2], b1l = Bl4[j >> 1][(j & 1) * 2 + 1];
                MMA16816(sS[j], Aq, b0h, b1h);
                MMA16816(sS[j], Aq, b0l, b1l);
                MMA16816(sS[j], Alr, b0h, b1h);
            }
        }

        // ---- mask + scale ----
        const int qrow0 = q0 + w * 16 + gr;
#pragma unroll
        for (int j = 0; j < 8; j++) {
#pragma unroll
            for (int e = 0; e < 4; e++) {
                int kg = k0 + j * 8 + gc2 + (e & 1);
                int qg = qrow0 + (e >> 1) * 8;
                bool ok = (kg <= qg) && (kg + WIN > qg);
                sS[j][e] = ok ? sS[j][e] * 0.125f : -1e30f;
            }
        }
        // ---- online softmax ----
        float rmax0 = -1e30f, rmax1 = -1e30f;
#pragma unroll
        for (int j = 0; j < 8; j++) {
            rmax0 = fmaxf(rmax0, fmaxf(sS[j][0], sS[j][1]));
            rmax1 = fmaxf(rmax1, fmaxf(sS[j][2], sS[j][3]));
        }
        rmax0 = fmaxf(rmax0, __shfl_xor_sync(0xffffffffu, rmax0, 1));
        rmax0 = fmaxf(rmax0, __shfl_xor_sync(0xffffffffu, rmax0, 2));
        rmax1 = fmaxf(rmax1, __shfl_xor_sync(0xffffffffu, rmax1, 1));
        rmax1 = fmaxf(rmax1, __shfl_xor_sync(0xffffffffu, rmax1, 2));
        const float mn0 = fmaxf(m0_, rmax0), mn1 = fmaxf(m1_, rmax1);
        const float al0 = __expf(m0_ - mn0), al1 = __expf(m1_ - mn1);
        float ps0 = 0.f, ps1 = 0.f;
#pragma unroll
        for (int j = 0; j < 8; j++) {
            float p0 = (sS[j][0] > -1e29f) ? __expf(sS[j][0] - mn0) : 0.f;
            float p1 = (sS[j][1] > -1e29f) ? __expf(sS[j][1] - mn0) : 0.f;
            float p2 = (sS[j][2] > -1e29f) ? __expf(sS[j][2] - mn1) : 0.f;
            float p3 = (sS[j][3] > -1e29f) ? __expf(sS[j][3] - mn1) : 0.f;
            ps0 += p0 + p1; ps1 += p2 + p3;
            sS[j][0] = p0; sS[j][1] = p1; sS[j][2] = p2; sS[j][3] = p3;
        }
        ps0 += __shfl_xor_sync(0xffffffffu, ps0, 1);
        ps0 += __shfl_xor_sync(0xffffffffu, ps0, 2);
        ps1 += __shfl_xor_sync(0xffffffffu, ps1, 1);
        ps1 += __shfl_xor_sync(0xffffffffu, ps1, 2);
        l0 = l0 * al0 + ps0;
        l1 = l1 * al1 + ps1;
        m0_ = mn0; m1_ = mn1;
#pragma unroll
        for (int j = 0; j < 8; j++) {
            O[j][0] *= al0; O[j][1] *= al0;
            O[j][2] *= al1; O[j][3] *= al1;
        }

        // ---- O += P @ V (3-term) ----
#pragma unroll
        for (int s = 0; s < 4; s++) {
            uint32_t pah[4], pal[4];
            split2(sS[2 * s][0], sS[2 * s][1], pah[0], pal[0]);
            split2(sS[2 * s][2], sS[2 * s][3], pah[1], pal[1]);
            split2(sS[2 * s + 1][0], sS[2 * s + 1][1], pah[2], pal[2]);
            split2(sS[2 * s + 1][2], sS[2 * s + 1][3], pah[3], pal[3]);

            uint32_t Vh4[4][4], Vl4[4][4];
            {
                int ksr = s * 16 + (lane & 7) + ((lane >> 3) & 1) * 8;
                uint32_t dby = ((lane >> 4) & 1) * 16;
#pragma unroll
                for (int dt = 0; dt < 4; dt++) {
                    LDSM_X4_T(Vh4[dt], sVh + ksr * ARS + dt * 32 + dby);
                    LDSM_X4_T(Vl4[dt], sVl + ksr * ARS + dt * 32 + dby);
                }
            }
#pragma unroll
            for (int j = 0; j < 8; j++) {
                uint32_t b0h = Vh4[j >> 1][(j & 1) * 2], b1h = Vh4[j >> 1][(j & 1) * 2 + 1];
                uint32_t b0l = Vl4[j >> 1][(j & 1) * 2], b1l = Vl4[j >> 1][(j & 1) * 2 + 1];
                MMA16816(O[j], pah, b0h, b1h);
                MMA16816(O[j], pah, b0l, b1l);
                MMA16816(O[j], pal, b0h, b1h);
            }
        }

        __syncthreads();                // everyone done reading K/V smem
        if (kt < qb) {
            load_kv(kt + 1);
            CP_WAIT0();
            __syncthreads();
        }
    }

    // ---- finalize: write split bf16 mixed [MROWS, DMODEL] ----
    const float i0 = 1.f / l0, i1 = 1.f / l1;
    const size_t row0 = (size_t)b * SQ + q0 + w * 16 + gr;
    const int colb = h * HDIM + gc2;
#pragma unroll
    for (int j = 0; j < 8; j++) {
        uint32_t hh, ll;
        split2(O[j][0] * i0, O[j][1] * i0, hh, ll);
        *(uint32_t*)(mixHi + row0 * DMODEL + colb + j * 8) = hh;
        *(uint32_t*)(mixLo + row0 * DMODEL + colb + j * 8) = ll;
        split2(O[j][2] * i1, O[j][3] * i1, hh, ll);
        *(uint32_t*)(mixHi + (row0 + 8) * DMODEL + colb + j * 8) = hh;
        *(uint32_t*)(mixLo + (row0 + 8) * DMODEL + colb + j * 8) = ll;
    }
}

// ---------------------------------------------------------------------------
extern "C" void kernel_launch(void* const* d_in, const int* in_sizes, int n_in,
                              void* d_out, int out_size)
{
    const float* normed = (const float*)d_in[0];
    // d_in[1] = attn_mask: analytic (k<=q && k>=q-255), unused
    const float* Wqkv = (const float*)d_in[2];
    const float* bqkv = (const float*)d_in[3];
    const float* Wout = (const float*)d_in[4];
    const float* bout = (const float*)d_in[5];
    float* out = (float*)d_out;

    __nv_bfloat16 *aHi, *aLo, *w1Hi, *w1Lo, *w2Hi, *w2Lo, *qkvHi, *qkvLo;
    cudaGetSymbolAddress((void**)&aHi, g_aHi);
    cudaGetSymbolAddress((void**)&aLo, g_aLo);
    cudaGetSymbolAddress((void**)&w1Hi, g_w1Hi);
    cudaGetSymbolAddress((void**)&w1Lo, g_w1Lo);
    cudaGetSymbolAddress((void**)&w2Hi, g_w2Hi);
    cudaGetSymbolAddress((void**)&w2Lo, g_w2Lo);
    cudaGetSymbolAddress((void**)&qkvHi, g_qkvHi);
    cudaGetSymbolAddress((void**)&qkvLo, g_qkvLo);

    cudaFuncSetAttribute(gemm_mma_kernel,
                         cudaFuncAttributeMaxDynamicSharedMemorySize, GSMEM);
    cudaFuncSetAttribute(attn_mma_kernel,
                         cudaFuncAttributeMaxDynamicSharedMemorySize, ASMEM);

    // 1) split/convert normed + Wqkv
    conv_act_kernel<<<MROWS, 256>>>(normed, aHi, aLo);
    conv_w_kernel<<<dim3(3 * DMODEL / 32, KDIM / 32), dim3(32, 8)>>>(Wqkv, w1Hi, w1Lo, 3 * DMODEL);

    // 2) qkv GEMM -> split bf16 qkv directly (no fp32 qkv)
    gemm_mma_kernel<<<dim3(3 * DMODEL / 256, MROWS / 128), 256, GSMEM>>>(
        aHi, aLo, w1Hi, w1Lo, bqkv, nullptr, qkvHi, qkvLo, 3 * DMODEL);

    // 3) tensor-core local attention -> split bf16 mixed (into aHi/aLo)
    dim3 g2(SQ / 64, NHEAD, BATCH);
    attn_mma_kernel<<<g2, 128, ASMEM>>>(qkvHi, qkvLo, aHi, aLo);

    // 4) Wout conversion + out GEMM (fp32 out)
    conv_w_kernel<<<dim3(DMODEL / 32, KDIM / 32), dim3(32, 8)>>>(Wout, w2Hi, w2Lo, DMODEL);
    gemm_mma_kernel<<<dim3(DMODEL / 256, MROWS / 128), 256, GSMEM>>>(
        aHi, aLo, w2Hi, w2Lo, bout, out, nullptr, nullptr, DMODEL);
}